// round 13
// baseline (speedup 1.0000x reference)
#include <cuda_runtime.h>

// Problem constants: B=16, N=8192, C=128, H=2, hd=64, G=2
#define NB 16
#define NN 8192
#define P 1024             // persistent blocks (148 SMs x 7 >= 1024 resident)
#define BPB 64             // blocks per b
#define CPB 4              // 32-row chunks per block (64*4*32 = 8192 rows/b)

// Scratch (device globals — zero-initialized; no allocation allowed)
__device__ float g_u[2 * 128];                // folded mem·Wk·scale  [h][cin]
__device__ float g_num[NB * 2 * BPB * 128];   // per-block partial Σ e·x (1 MB)
__device__ float g_den[NB * 2 * BPB];         // per-block partial Σ e
__device__ unsigned g_cnt;                    // barrier counter (resets each use)
__device__ unsigned g_epoch;                  // barrier epoch (monotonic)

// ---------------------------------------------------------------------------
// u-prep node (1 block; PDL trigger). Wk staged via coalesced float4 loads
// (R10 lesson: strided cold loads made the naive version the longest kernel).
// ---------------------------------------------------------------------------
__global__ void k_prep_u(const float* __restrict__ Wk, const float* __restrict__ mem) {
    __shared__ float sW[8192];
    __shared__ float sm[128];
    int t = threadIdx.x;                // 256 threads

    float4* sW4 = (float4*)sW;
    const float4* gW4 = (const float4*)Wk;
#pragma unroll
    for (int k = 0; k < 8; ++k)
        sW4[t + 256 * k] = __ldg(gW4 + t + 256 * k);
    if (t < 128) sm[t] = mem[t];
    __syncthreads();

    int h = t >> 7, cin = t & 127, g = cin >> 6, i = cin & 63;
    float acc = 0.f;
#pragma unroll
    for (int j = 0; j < 32; ++j)
        acc += sm[h * 64 + 2 * j + g] * sW[(g * 64 + h * 32 + j) * 64 + i];
    g_u[t] = acc * 0.125f;              // scale = hd^-0.5 = 1/8
    __threadfence();
    cudaTriggerProgrammaticLaunchCompletion();
}

// Epoch grid barrier (replay-idempotent: counter returns to 0, epoch grows).
__device__ __forceinline__ void gbar() {
    __threadfence();
    __syncthreads();
    if (threadIdx.x == 0) {
        unsigned e0 = *((volatile unsigned*)&g_epoch);
        unsigned prev = atomicAdd(&g_cnt, 1u);
        if (prev == (unsigned)P - 1u) {
            atomicExch(&g_cnt, 0u);
            __threadfence();
            atomicAdd(&g_epoch, 1u);
        } else {
            while (*((volatile unsigned*)&g_epoch) == e0) __nanosleep(32);
            __threadfence();
        }
    }
    __syncthreads();
}

// ---------------------------------------------------------------------------
// Persistent main kernel: phase1 = R8's register-butterfly fused loop over 4
// chunks (accumulate in regs), one partial per (block, head); ONE grid
// barrier; phase2 = per-block finalize for the ONE head this block's output
// slice needs; phase3 = write own 128-row slice.
// ---------------------------------------------------------------------------
__global__ __launch_bounds__(128, 7) void k_main(
    const float* __restrict__ x,  const float* __restrict__ Wv,
    const float* __restrict__ Wp, const float* __restrict__ bp,
    float4* __restrict__ out)
{
    __shared__ float4 sacc[2][4][32];
    __shared__ float  sden[2][4];
    __shared__ float  sd[BPB];
    __shared__ float  xa[128];
    __shared__ float  rowv[64];
    __shared__ __align__(16) float sfv[128];

    int t = threadIdx.x, w = t >> 5, lane = t & 31;
    int b = blockIdx.x >> 6;            // 64 blocks per b
    int l = blockIdx.x & 63;            // block's slot: rows [l*128, l*128+128)

    // Pre-issue chunk-0 loads before the PDL wait (independent of g_u).
    const float4* xbase = (const float4*)x
        + ((size_t)b * NN + (size_t)l * 128 + (size_t)w * 8) * 32 + lane;
    float4 v[8];
#pragma unroll
    for (int k = 0; k < 8; ++k) v[k] = __ldcs(xbase + k * 32);

    cudaGridDependencySynchronize();    // g_u ready

    float4 u0 = ((const float4*)g_u)[lane];
    float4 u1 = ((const float4*)g_u)[32 + lane];

    float4 a0 = make_float4(0.f, 0.f, 0.f, 0.f);
    float4 a1 = make_float4(0.f, 0.f, 0.f, 0.f);
    float den0 = 0.f, den1 = 0.f;
    bool odd = lane & 1;

    for (int c4 = 0; c4 < CPB; ++c4) {
        if (c4 > 0) {                   // load this chunk (chunk 0 pre-issued)
#pragma unroll
            for (int k = 0; k < 8; ++k)
                v[k] = __ldcs(xbase + (size_t)c4 * 1024 + k * 32);
        }
#pragma unroll
        for (int k = 0; k < 8; ++k) {
            float4 xv = v[k];
            float p0 = xv.x * u0.x + xv.y * u0.y + xv.z * u0.z + xv.w * u0.w;
            float p1 = xv.x * u1.x + xv.y * u1.y + xv.z * u1.z + xv.w * u1.w;
            // folded two-head butterfly (R8-proven)
            float aa = p0 + __shfl_xor_sync(0xffffffffu, p0, 1);
            float bb = p1 + __shfl_xor_sync(0xffffffffu, p1, 1);
            float c = odd ? bb : aa;        // even lanes h0, odd lanes h1
            c += __shfl_xor_sync(0xffffffffu, c, 2);
            c += __shfl_xor_sync(0xffffffffu, c, 4);
            c += __shfl_xor_sync(0xffffffffu, c, 8);
            c += __shfl_xor_sync(0xffffffffu, c, 16);
            float d = __shfl_xor_sync(0xffffffffu, c, 1);
            float s0 = odd ? d : c;
            float s1 = odd ? c : d;
            float e0 = __expf(s0);          // no max shift; logits are O(1)
            float e1 = __expf(s1);
            a0.x += e0 * xv.x; a0.y += e0 * xv.y; a0.z += e0 * xv.z; a0.w += e0 * xv.w;
            a1.x += e1 * xv.x; a1.y += e1 * xv.y; a1.z += e1 * xv.z; a1.w += e1 * xv.w;
            den0 += e0; den1 += e1;
        }
    }

    sacc[0][w][lane] = a0;
    sacc[1][w][lane] = a1;
    if (lane == 0) { sden[0][w] = den0; sden[1][w] = den1; }
    __syncthreads();

    if (t < 64) {
        int h = t >> 5, c = t & 31;
        float4 r = sacc[h][0][c];
#pragma unroll
        for (int ww = 1; ww < 4; ++ww) {
            float4 p = sacc[h][ww][c];
            r.x += p.x; r.y += p.y; r.z += p.z; r.w += p.w;
        }
        ((float4*)g_num)[((size_t)(b * 2 + h) * BPB + l) * 32 + c] = r;
    } else if (t < 66) {
        int h = t - 64;
        g_den[(size_t)(b * 2 + h) * BPB + l]
            = sden[h][0] + sden[h][1] + sden[h][2] + sden[h][3];
    }

    gbar();                             // the ONE grid barrier

    // ---- phase 2: finalize the single head this block's slice needs ----
    int half = l >> 5;                  // rows l*128.. are in half (l>=32)
    int bh = b * 2 + half;
    {
        const float* np = g_num + (size_t)bh * BPB * 128;
        float s = 0.f;
#pragma unroll 8
        for (int j = 0; j < BPB; ++j) s += np[(size_t)j * 128 + t];
        if (t < BPB) sd[t] = g_den[(size_t)bh * BPB + t];
        __syncthreads();
        float d = 0.f;
#pragma unroll
        for (int j = 0; j < BPB; ++j) d += sd[j];    // broadcast LDS, fixed order
        xa[t] = s / d;
    }
    __syncthreads();

    if (t < 64) {   // rowv[d] = Σ_i xa[g*64+i] · Wv[g, half*32+d/2, i], g=d%2
        int g = t & 1, o = half * 32 + (t >> 1);
        const float* wv = Wv + (g * 64 + o) * 64;
        const float* xv = xa + g * 64;
        float acc = 0.f;
#pragma unroll
        for (int i = 0; i < 64; ++i) acc += xv[i] * wv[i];
        rowv[t] = acc;
    }
    __syncthreads();

    {   // sfv[c2] = bp[g2,o2] + Σ_i rowv[i] · Wp[g2,o2,i]
        int g2 = t & 1, o2 = t >> 1;
        const float* wp = Wp + (g2 * 64 + o2) * 64;
        float f = bp[g2 * 64 + o2];
#pragma unroll
        for (int i = 0; i < 64; ++i) f += rowv[i] * wp[i];
        sfv[t] = f;
    }
    __syncthreads();

    // ---- phase 3: write own 128-row slice (64 KB, coalesced STG.128) ----
    {
        float4 vv = ((const float4*)sfv)[t & 31];
        float4* dst = out + ((size_t)b * NN + (size_t)l * 128) * 32;
#pragma unroll 8
        for (int k = 0; k < 32; ++k)
            __stcs(dst + k * 128 + t, vv);  // (k*128+t)%32 == t%32 -> channel ok
    }
}

// ---------------------------------------------------------------------------
extern "C" void kernel_launch(void* const* d_in, const int* in_sizes, int n_in,
                              void* d_out, int out_size) {
    const float* x   = (const float*)d_in[0];
    const float* Wk  = (const float*)d_in[1];
    const float* Wv  = (const float*)d_in[2];
    const float* Wp  = (const float*)d_in[3];
    const float* bp  = (const float*)d_in[4];
    const float* mem = (const float*)d_in[5];
    float4* out = (float4*)d_out;

    k_prep_u<<<1, 256>>>(Wk, mem);

    cudaLaunchAttribute at[1];
    at[0].id = cudaLaunchAttributeProgrammaticStreamSerialization;
    at[0].val.programmaticStreamSerializationAllowed = 1;
    cudaLaunchConfig_t cfg = {};
    cfg.stream = 0;
    cfg.attrs = at;
    cfg.numAttrs = 1;
    cfg.gridDim = dim3(P);
    cfg.blockDim = dim3(128);
    cudaLaunchKernelEx(&cfg, k_main, x, Wv, Wp, bp, out);
}

// round 14
// speedup vs baseline: 1.7959x; 1.7959x over previous
#include <cuda_runtime.h>

// Problem constants: B=16, N=8192, C=128, H=2, hd=64, G=2
#define NB 16
#define NN 8192
#define NCH 256            // 32-row chunks per b

// Scratch (device globals — no allocation allowed)
__device__ float g_u[2 * 128];                  // folded mem·Wk·scale  [h][cin]
__device__ float g_num[NB * 2 * NCH * 128];     // per-chunk partial Σ e·x (4 MB)
__device__ float g_den[NB * 2 * NCH];           // per-chunk partial Σ e
__device__ float g_fv[NB * 2 * 128];            // final vectors [b][half][c]

// ---------------------------------------------------------------------------
// u[h, g*64+i] = scale * sum_j mem[h, 2j+g] * Wk[g, h*32+j, i]
// Wk staged via coalesced float4 loads (R10 lesson).
// ---------------------------------------------------------------------------
__global__ void k_prep_u(const float* __restrict__ Wk, const float* __restrict__ mem) {
    __shared__ float sW[8192];
    __shared__ float sm[128];
    int t = threadIdx.x;                // 256 threads

    float4* sW4 = (float4*)sW;
    const float4* gW4 = (const float4*)Wk;
#pragma unroll
    for (int k = 0; k < 8; ++k)
        sW4[t + 256 * k] = __ldg(gW4 + t + 256 * k);
    if (t < 128) sm[t] = mem[t];
    __syncthreads();

    int h = t >> 7, cin = t & 127, g = cin >> 6, i = cin & 63;
    float acc = 0.f;
#pragma unroll
    for (int j = 0; j < 32; ++j)
        acc += sm[h * 64 + 2 * j + g] * sW[(g * 64 + h * 32 + j) * 64 + i];
    g_u[t] = acc * 0.125f;              // scale = hd^-0.5 = 1/8
}

// ---------------------------------------------------------------------------
// FUSED half-batch (8 b's): register-only logits + exp (no max shift; logits
// are O(1) by construction) + weighted accumulate, folded two-head butterfly.
// grid = 2048 x 128.
// ---------------------------------------------------------------------------
__global__ __launch_bounds__(128) void k_fused(const float* __restrict__ x, int b0) {
    __shared__ float4 sacc[2][4][32];
    __shared__ float  sden[2][4];

    int t = threadIdx.x, w = t >> 5, lane = t & 31;
    int b = b0 + (blockIdx.x >> 8);
    int chunk = blockIdx.x & (NCH - 1);

    const float4* xb = (const float4*)x
        + ((size_t)b * NN + (size_t)chunk * 32 + (size_t)w * 8) * 32 + lane;
    float4 v[8];
#pragma unroll
    for (int k = 0; k < 8; ++k) v[k] = __ldcs(xb + k * 32);

    float4 u0 = ((const float4*)g_u)[lane];
    float4 u1 = ((const float4*)g_u)[32 + lane];

    float4 a0 = make_float4(0.f, 0.f, 0.f, 0.f);
    float4 a1 = make_float4(0.f, 0.f, 0.f, 0.f);
    float den0 = 0.f, den1 = 0.f;
    bool odd = lane & 1;

#pragma unroll
    for (int k = 0; k < 8; ++k) {
        float4 xv = v[k];
        float p0 = xv.x * u0.x + xv.y * u0.y + xv.z * u0.z + xv.w * u0.w;
        float p1 = xv.x * u1.x + xv.y * u1.y + xv.z * u1.z + xv.w * u1.w;
        float aa = p0 + __shfl_xor_sync(0xffffffffu, p0, 1);
        float bb = p1 + __shfl_xor_sync(0xffffffffu, p1, 1);
        float c = odd ? bb : aa;            // even lanes carry h0, odd h1
        c += __shfl_xor_sync(0xffffffffu, c, 2);
        c += __shfl_xor_sync(0xffffffffu, c, 4);
        c += __shfl_xor_sync(0xffffffffu, c, 8);
        c += __shfl_xor_sync(0xffffffffu, c, 16);
        float d = __shfl_xor_sync(0xffffffffu, c, 1);
        float s0 = odd ? d : c;
        float s1 = odd ? c : d;
        float e0 = __expf(s0);
        float e1 = __expf(s1);
        a0.x += e0 * xv.x; a0.y += e0 * xv.y; a0.z += e0 * xv.z; a0.w += e0 * xv.w;
        a1.x += e1 * xv.x; a1.y += e1 * xv.y; a1.z += e1 * xv.z; a1.w += e1 * xv.w;
        den0 += e0; den1 += e1;
    }

    sacc[0][w][lane] = a0;
    sacc[1][w][lane] = a1;
    if (lane == 0) { sden[0][w] = den0; sden[1][w] = den1; }
    __syncthreads();

    if (t < 64) {
        int h = t >> 5, c = t & 31;
        float4 r = sacc[h][0][c];
#pragma unroll
        for (int ww = 1; ww < 4; ++ww) {
            float4 p = sacc[h][ww][c];
            r.x += p.x; r.y += p.y; r.z += p.z; r.w += p.w;
        }
        ((float4*)g_num)[((size_t)(b * 2 + h) * NCH + chunk) * 32 + c] = r;
    } else if (t < 66) {
        int h = t - 64;
        g_den[(size_t)(b * 2 + h) * NCH + chunk]
            = sden[h][0] + sden[h][1] + sden[h][2] + sden[h][3];
    }
}

// ---------------------------------------------------------------------------
// Finalize half-batch: one block per (b,h). 16 blocks x 1024 threads.
// ---------------------------------------------------------------------------
__global__ __launch_bounds__(1024) void k_final(const float* __restrict__ Wv,
                                                const float* __restrict__ Wp,
                                                const float* __restrict__ bp,
                                                int bh0) {
    int bh = bh0 + blockIdx.x, b = bh >> 1, h = bh & 1;
    int t = threadIdx.x;
    __shared__ float sred[8][128];
    __shared__ float sdn[8];
    __shared__ float xa[128];
    __shared__ float row[64];

    int c = t & 127, slice = t >> 7;    // 8 slices x 32 chunks
    const float* base = g_num + (size_t)bh * NCH * 128;
    float a = 0.f;
#pragma unroll
    for (int j = 0; j < 32; ++j)
        a += base[(size_t)(slice * 32 + j) * 128 + c];
    sred[slice][c] = a;

    if (t < 256) {
        float d = g_den[(size_t)bh * NCH + t];
#pragma unroll
        for (int off = 16; off > 0; off >>= 1)
            d += __shfl_xor_sync(0xffffffffu, d, off);
        if ((t & 31) == 0) sdn[t >> 5] = d;
    }
    __syncthreads();

    if (t < 128) {
        float s = 0.f;
#pragma unroll
        for (int sl = 0; sl < 8; ++sl) s += sred[sl][t];
        float dd = sdn[0] + sdn[1] + sdn[2] + sdn[3]
                 + sdn[4] + sdn[5] + sdn[6] + sdn[7];
        xa[t] = s / dd;
    }
    __syncthreads();

    if (t < 64) {                        // row[d] = Σ_i xa[g*64+i]·Wv[g,h*32+d/2,i]
        int g = t & 1, o = h * 32 + (t >> 1);
        const float* w = Wv + (g * 64 + o) * 64;
        const float* xv = xa + g * 64;
        float acc = 0.f;
#pragma unroll
        for (int i = 0; i < 64; ++i) acc += xv[i] * w[i];
        row[t] = acc;
    }
    __syncthreads();

    if (t < 128) {                       // fv = row·Wp + bp (half == h)
        int g2 = t & 1, o2 = t >> 1;
        const float* w = Wp + (g2 * 64 + o2) * 64;
        float f = bp[g2 * 64 + o2];
#pragma unroll
        for (int i = 0; i < 64; ++i) f += row[i] * w[i];
        g_fv[(size_t)b * 256 + h * 128 + t] = f;
    }
}

// ---------------------------------------------------------------------------
// Broadcast half-batch (32 MB): 512 blocks x 256 threads, fv in a register,
// 16 coalesced streaming STG.128 each.
// ---------------------------------------------------------------------------
__global__ __launch_bounds__(256) void k_bcast(float4* __restrict__ out, int bh0) {
    int t = threadIdx.x;
    int bh = bh0 + (blockIdx.x >> 5);  // 32 segment-blocks per (b,half)
    int seg = blockIdx.x & 31;
    float4* dst = out + (size_t)bh * 131072 + (size_t)seg * 4096;

    float4 v = __ldg((const float4*)g_fv + (size_t)bh * 32 + (t & 31));
#pragma unroll
    for (int k = 0; k < 16; ++k)
        __stcs(dst + k * 256 + t, v);  // channel (addr%32) matches t%32
}

// ---------------------------------------------------------------------------
// Two parallel graph branches: fork after fusedA so fusedB's 32MB DRAM read
// co-runs with finalA+bcastA's write phase. Streams/events are static infra
// handles (created once, host-side); the captured WORK is identical per call.
// ---------------------------------------------------------------------------
extern "C" void kernel_launch(void* const* d_in, const int* in_sizes, int n_in,
                              void* d_out, int out_size) {
    const float* x   = (const float*)d_in[0];
    const float* Wk  = (const float*)d_in[1];
    const float* Wv  = (const float*)d_in[2];
    const float* Wp  = (const float*)d_in[3];
    const float* bp  = (const float*)d_in[4];
    const float* mem = (const float*)d_in[5];
    float4* out = (float4*)d_out;

    static cudaStream_t s1 = nullptr;
    static cudaEvent_t evFork = nullptr, evJoin = nullptr;
    if (s1 == nullptr) {
        cudaStreamCreateWithFlags(&s1, cudaStreamNonBlocking);
        cudaEventCreateWithFlags(&evFork, cudaEventDisableTiming);
        cudaEventCreateWithFlags(&evJoin, cudaEventDisableTiming);
    }

    // ---- trunk (capture stream) ----
    k_prep_u<<<1, 256>>>(Wk, mem);
    k_fused<<<8 * NCH, 128>>>(x, 0);                 // read half A (b 0..7)

    // fork: branch B depends only on fusedA (for g_u ordering via prep)
    cudaEventRecord(evFork, 0);
    cudaStreamWaitEvent(s1, evFork, 0);

    // ---- branch A (capture stream): finalize + write half A ----
    k_final<<<16, 1024>>>(Wv, Wp, bp, 0);
    k_bcast<<<512, 256>>>(out, 0);

    // ---- branch B (s1): read half B overlaps branch A's write ----
    k_fused<<<8 * NCH, 128, 0, s1>>>(x, 8);          // b 8..15
    k_final<<<16, 1024, 0, s1>>>(Wv, Wp, bp, 16);
    k_bcast<<<512, 256, 0, s1>>>(out, 16);

    // join
    cudaEventRecord(evJoin, s1);
    cudaStreamWaitEvent(0, evJoin, 0);
}